// round 16
// baseline (speedup 1.0000x reference)
#include <cuda_runtime.h>
#include <cuda_bf16.h>
#include <cuda_fp16.h>
#include <cstdint>

#define N_NODES 50000
#define N_PAD   50048          // 391 * 128
#define R_REL   16
#define B_BASES 8
#define DIN     128
#define DOUT    128
#define NNZ     1600000
#define M_TILES 391
#define SCAN_BLKS 49           // ceil(50000/1024)

typedef unsigned int uint;

// Scratch: device globals (no allocation allowed)
__device__ __half g_X16[(size_t)N_PAD * DIN];               // 12.8 MB (fp16 X)
__device__ __half g_BT16[B_BASES * DOUT * DIN];             // 256 KB (BT[b][n][k])
__device__ __half g_XB[(size_t)B_BASES * N_NODES * DOUT];   // 102.4 MB (fp16)
__device__ __half g_FW[(size_t)R_REL * N_NODES * DOUT];     // 204.8 MB (fp16)
__device__ int    g_idx64;
// CSR binning scratch
__device__ int   g_cnt[N_NODES];
__device__ int   g_start[N_NODES + 1];
__device__ int   g_cursor[N_NODES];
__device__ int   g_bsum[SCAN_BLKS];
__device__ int2  g_edge[NNZ];

// ---------------------------------------------------------------------------
__device__ __forceinline__ uint32_t smem_u32(const void* p) {
    uint32_t a;
    asm("{ .reg .u64 t; cvta.to.shared.u64 t, %1; cvt.u32.u64 %0, t; }"
        : "=r"(a) : "l"(p));
    return a;
}
__device__ __forceinline__ void ldsm_x4(uint r[4], uint32_t addr) {
    asm volatile("ldmatrix.sync.aligned.m8n8.x4.shared.b16 {%0,%1,%2,%3}, [%4];"
                 : "=r"(r[0]), "=r"(r[1]), "=r"(r[2]), "=r"(r[3]) : "r"(addr));
}
__device__ __forceinline__ void mma_f16(float c[4], const uint a[4], const uint b0, const uint b1) {
    asm volatile("mma.sync.aligned.m16n8k16.row.col.f32.f16.f16.f32 "
                 "{%0,%1,%2,%3},{%4,%5,%6,%7},{%8,%9},{%0,%1,%2,%3};"
                 : "+f"(c[0]), "+f"(c[1]), "+f"(c[2]), "+f"(c[3])
                 : "r"(a[0]), "r"(a[1]), "r"(a[2]), "r"(a[3]), "r"(b0), "r"(b1));
}
__device__ __forceinline__ void cp_async16(uint32_t dst, const void* src) {
    asm volatile("cp.async.cg.shared.global [%0], [%1], 16;" :: "r"(dst), "l"(src));
}
#define CP_COMMIT() asm volatile("cp.async.commit_group;" ::: "memory")
#define CP_WAIT(n)  asm volatile("cp.async.wait_group %0;" :: "n"(n) : "memory")

// ---------------------------------------------------------------------------
__global__ void detect_dtype_kernel(const unsigned int* __restrict__ rows_raw) {
    bool all_hi_zero = true;
    for (int i = 0; i < 64; i++)
        if (rows_raw[2 * i + 1] != 0u) { all_hi_zero = false; break; }
    g_idx64 = all_hi_zero ? 1 : 0;
}

__global__ void zero_cnt_kernel() {
    int i = blockIdx.x * blockDim.x + threadIdx.x;
    if (i < N_NODES) g_cnt[i] = 0;
}

__global__ void hist_kernel(const void* __restrict__ rows) {
    const int e = blockIdx.x * blockDim.x + threadIdx.x;
    if (e >= NNZ) return;
    int row = g_idx64 ? (int)((const unsigned int*)rows)[2 * e]
                      : ((const int*)rows)[e];
    atomicAdd(&g_cnt[row], 1);
}

// --- 3-phase multi-block exclusive scan of g_cnt -> g_start / g_cursor ---
__global__ void __launch_bounds__(1024) scan1_kernel() {
    __shared__ int wsum[32];
    const int tid = threadIdx.x, lane = tid & 31, wid = tid >> 5;
    const int i = blockIdx.x * 1024 + tid;
    int v = (i < N_NODES) ? g_cnt[i] : 0;
    int x = v;
#pragma unroll
    for (int off = 1; off < 32; off <<= 1) {
        int y = __shfl_up_sync(0xffffffffu, x, off);
        if (lane >= off) x += y;
    }
    if (lane == 31) wsum[wid] = x;
    __syncthreads();
    if (wid == 0) {
        int s = wsum[lane];
#pragma unroll
        for (int off = 1; off < 32; off <<= 1) {
            int y = __shfl_up_sync(0xffffffffu, s, off);
            if (lane >= off) s += y;
        }
        wsum[lane] = s;
    }
    __syncthreads();
    const int warpOff = (wid == 0) ? 0 : wsum[wid - 1];
    if (i < N_NODES) g_start[i] = warpOff + x - v;
    if (tid == 0) g_bsum[blockIdx.x] = wsum[31];
}

__global__ void __launch_bounds__(64) scan2_kernel() {
    __shared__ int s[SCAN_BLKS];
    const int tid = threadIdx.x;
    if (tid < SCAN_BLKS) s[tid] = g_bsum[tid];
    __syncthreads();
    if (tid == 0) {
        int run = 0;
        for (int k = 0; k < SCAN_BLKS; k++) { int v = s[k]; s[k] = run; run += v; }
        g_start[N_NODES] = NNZ;
    }
    __syncthreads();
    if (tid < SCAN_BLKS) g_bsum[tid] = s[tid];
}

__global__ void __launch_bounds__(1024) scan3_kernel() {
    const int i = blockIdx.x * 1024 + threadIdx.x;
    if (i >= N_NODES) return;
    const int v = g_start[i] + g_bsum[blockIdx.x];
    g_start[i]  = v;
    g_cursor[i] = v;
}

__global__ void fill_kernel(const void* __restrict__ rows,
                            const void* __restrict__ cols,
                            const float* __restrict__ vals) {
    const int e = blockIdx.x * blockDim.x + threadIdx.x;
    if (e >= NNZ) return;
    int row, col;
    if (g_idx64) {
        row = (int)((const unsigned int*)rows)[2 * e];
        col = (int)((const unsigned int*)cols)[2 * e];
    } else {
        row = ((const int*)rows)[e];
        col = ((const int*)cols)[e];
    }
    const int pos = atomicAdd(&g_cursor[row], 1);
    g_edge[pos] = make_int2(col, __float_as_int(vals[e]));
}

// ---------------------------------------------------------------------------
__global__ void prep_x_kernel(const float* __restrict__ X) {
    const int id = blockIdx.x * blockDim.x + threadIdx.x;
    if (id >= (N_PAD * DIN) / 8) return;
    const size_t base = (size_t)id * 8;
    const int row = (int)(base >> 7);
    __half h[8];
    if (row < N_NODES) {
        float v[8];
        *(float4*)&v[0] = *(const float4*)(X + base);
        *(float4*)&v[4] = *(const float4*)(X + base + 4);
#pragma unroll
        for (int i = 0; i < 8; i++) h[i] = __float2half_rn(v[i]);
    } else {
#pragma unroll
        for (int i = 0; i < 8; i++) h[i] = __float2half_rn(0.f);
    }
    *(uint4*)(g_X16 + base) = *(uint4*)h;
}

__global__ void prep_bt_kernel(const float* __restrict__ basis) {
    const int id = blockIdx.x * blockDim.x + threadIdx.x;
    if (id >= B_BASES * DOUT * (DIN / 4)) return;
    const int k4 = (id & 31) * 4;
    const int n  = (id >> 5) & 127;
    const int b  = id >> 12;
    __half h[4];
#pragma unroll
    for (int i = 0; i < 4; i++)
        h[i] = __float2half_rn(basis[(size_t)b * DIN * DOUT + (size_t)(k4 + i) * DOUT + n]);
    const size_t off = (size_t)b * DOUT * DIN + (size_t)n * DIN + k4;
    *(uint2*)(g_BT16 + off) = *(uint2*)h;
}

// ---------------------------------------------------------------------------
// XB[b] = X @ basis[b] via single-product fp16 mma.sync (R13 exact).
// ---------------------------------------------------------------------------
#define S_B    0
#define S_X    32768
#define XBUF   8192
#define S_TOTAL 49152

__global__ void __launch_bounds__(256, 2)
gemm_mma_kernel(int dummy) {
    extern __shared__ __align__(1024) unsigned char smem[];
    const uint32_t sbase = smem_u32(smem);
    const int tid  = threadIdx.x;
    const int wid  = tid >> 5;
    const int lane = tid & 31;
    const int b    = blockIdx.y;
    const int m0   = blockIdx.x * 128;

    const int wm = wid >> 1;
    const int wn = wid & 1;

    {
        const size_t bBase = (size_t)b * DOUT * DIN;
#pragma unroll
        for (int i = 0; i < 8; i++) {
            const int slot = i * 256 + tid;
            const int row  = slot >> 4;
            const int c    = slot & 15;
            const uint32_t dst = (uint32_t)(row * 256 + ((c ^ (row & 7)) << 4));
            cp_async16(sbase + S_B + dst, g_BT16 + bBase + (size_t)row * DIN + c * 8);
        }
    }
    CP_COMMIT();
#pragma unroll
    for (int i = 0; i < 2; i++) {
        const int s2  = i * 256 + tid;
        const int row = s2 >> 2;
        const int c   = s2 & 3;
        const uint32_t dst = (uint32_t)(row * 64 + ((c ^ ((row >> 1) & 3)) << 4));
        cp_async16(sbase + S_X + dst, g_X16 + (size_t)(m0 + row) * DIN + c * 8);
    }
    CP_COMMIT();

    float acc[2][8][4];
#pragma unroll
    for (int mf = 0; mf < 2; mf++)
#pragma unroll
        for (int nf = 0; nf < 8; nf++)
#pragma unroll
            for (int q = 0; q < 4; q++) acc[mf][nf][q] = 0.f;

    const int a_row0 = wm * 32 + (lane & 15);
    const int a_ch   = lane >> 4;
    const int b_row0 = wn * 64 + (lane & 7) + ((lane >> 4) << 3);
    const int b_ch   = (lane >> 3) & 1;

#pragma unroll
    for (int kc = 0; kc < 4; kc++) {
        if (kc < 3) {
            const uint32_t xb = sbase + S_X + ((kc + 1) & 1) * XBUF;
#pragma unroll
            for (int i = 0; i < 2; i++) {
                const int s2  = i * 256 + tid;
                const int row = s2 >> 2;
                const int c   = s2 & 3;
                const uint32_t dst = (uint32_t)(row * 64 + ((c ^ ((row >> 1) & 3)) << 4));
                cp_async16(xb + dst, g_X16 + (size_t)(m0 + row) * DIN + (kc + 1) * 32 + c * 8);
            }
            CP_COMMIT();
            CP_WAIT(1);
        } else {
            CP_WAIT(0);
        }
        __syncthreads();

        const uint32_t xh = sbase + S_X + (kc & 1) * XBUF;

#pragma unroll
        for (int kfi = 0; kfi < 2; kfi++) {
            const int kf = kc * 2 + kfi;
            uint A[2][4];
#pragma unroll
            for (int mf = 0; mf < 2; mf++) {
                const int row = a_row0 + mf * 16;
                const uint32_t addr = (uint32_t)(row * 64 +
                    (((kfi * 2 + a_ch) ^ ((row >> 1) & 3)) << 4));
                ldsm_x4(A[mf], xh + addr);
            }
#pragma unroll
            for (int p = 0; p < 4; p++) {
                const int row = b_row0 + p * 16;
                const uint32_t addr = (uint32_t)(row * 256 +
                    (((kf * 2 + b_ch) ^ (row & 7)) << 4));
                uint B[4];
                ldsm_x4(B, sbase + S_B + addr);
#pragma unroll
                for (int mf = 0; mf < 2; mf++) {
                    mma_f16(acc[mf][2 * p],     A[mf], B[0], B[1]);
                    mma_f16(acc[mf][2 * p + 1], A[mf], B[2], B[3]);
                }
            }
        }
        __syncthreads();
    }

    __half* outBase = g_XB + (size_t)b * N_NODES * DOUT;
    const int g = lane >> 2;
    const int t2 = (lane & 3) * 2;
#pragma unroll
    for (int mf = 0; mf < 2; mf++) {
        const int r0 = m0 + wm * 32 + mf * 16 + g;
#pragma unroll
        for (int nf = 0; nf < 8; nf++) {
            const int col = wn * 64 + nf * 8 + t2;
            if (r0 < N_NODES) {
                __half2 h = __floats2half2_rn(acc[mf][nf][0], acc[mf][nf][1]);
                *(uint32_t*)(outBase + (size_t)r0 * DOUT + col) = *(uint32_t*)&h;
            }
            if (r0 + 8 < N_NODES) {
                __half2 h = __floats2half2_rn(acc[mf][nf][2], acc[mf][nf][3]);
                *(uint32_t*)(outBase + (size_t)(r0 + 8) * DOUT + col) = *(uint32_t*)&h;
            }
        }
    }
}

// ---------------------------------------------------------------------------
// combine half: FW[r][n][d] = sum_b comp[r][b]*XB[b][n][d], d in one 64-half.
// ---------------------------------------------------------------------------
__global__ __launch_bounds__(256)
void combine_half_kernel(const float* __restrict__ comp, int dhalf) {
    __shared__ float cs[R_REL * B_BASES];
    if (threadIdx.x < R_REL * B_BASES) cs[threadIdx.x] = comp[threadIdx.x];
    __syncthreads();

    const int id = blockIdx.x * blockDim.x + threadIdx.x;
    if (id >= N_NODES * 16) return;
    const int n  = id >> 4;
    const int d4 = (dhalf * 16 + (id & 15)) * 4;

    float4 xb[8];
#pragma unroll
    for (int b = 0; b < B_BASES; b++) {
        const uint2 pk = __ldg((const uint2*)(g_XB + ((size_t)b * N_NODES + n) * DOUT + d4));
        const float2 a = __half22float2(*(const __half2*)&pk.x);
        const float2 c = __half22float2(*(const __half2*)&pk.y);
        xb[b] = make_float4(a.x, a.y, c.x, c.y);
    }

#pragma unroll
    for (int r = 0; r < R_REL; r++) {
        float4 o = make_float4(0.f, 0.f, 0.f, 0.f);
#pragma unroll
        for (int b = 0; b < B_BASES; b++) {
            const float c = cs[r * B_BASES + b];
            o.x += c * xb[b].x;
            o.y += c * xb[b].y;
            o.z += c * xb[b].z;
            o.w += c * xb[b].w;
        }
        __half2 h0 = __floats2half2_rn(o.x, o.y);
        __half2 h1 = __floats2half2_rn(o.z, o.w);
        uint2 pk;
        pk.x = *(uint32_t*)&h0;
        pk.y = *(uint32_t*)&h1;
        *(uint2*)(g_FW + ((size_t)r * N_NODES + n) * DOUT + d4) = pk;
    }
}

// ---------------------------------------------------------------------------
// scatter half: one warp per out row; 16 lanes x uint2 per edge (LDG.64 kept),
// two edges per iteration (lane>>4 selects edge), shfl_xor(16) reduction.
// ---------------------------------------------------------------------------
__global__ void __launch_bounds__(256)
scatter_half_kernel(float* __restrict__ out, int dhalf) {
    const int warpId = (blockIdx.x * blockDim.x + threadIdx.x) >> 5;
    if (warpId >= N_NODES) return;
    const int lane   = threadIdx.x & 31;
    const int lane16 = lane & 15;
    const int sel    = lane >> 4;
    const int dOff   = dhalf * 64;

    const int s = g_start[warpId];
    const int e = g_start[warpId + 1];

    float4 acc = make_float4(0.f, 0.f, 0.f, 0.f);
    int i = s;
    // 4 edge-pairs (8 edges) per iteration for MLP
    for (; i + 8 <= e; i += 8) {
        int2 ed[4];
        uint2 pk[4];
#pragma unroll
        for (int q = 0; q < 4; q++) ed[q] = __ldg(&g_edge[i + q * 2 + sel]);
#pragma unroll
        for (int q = 0; q < 4; q++)
            pk[q] = __ldg((const uint2*)(g_FW + (size_t)ed[q].x * DOUT + dOff) + lane16);
#pragma unroll
        for (int q = 0; q < 4; q++) {
            const float v = __int_as_float(ed[q].y);
            const float2 a = __half22float2(*(const __half2*)&pk[q].x);
            const float2 b = __half22float2(*(const __half2*)&pk[q].y);
            acc.x += v * a.x; acc.y += v * a.y; acc.z += v * b.x; acc.w += v * b.y;
        }
    }
    for (; i + 2 <= e; i += 2) {
        int2 ed = __ldg(&g_edge[i + sel]);
        uint2 pk = __ldg((const uint2*)(g_FW + (size_t)ed.x * DOUT + dOff) + lane16);
        const float v = __int_as_float(ed.y);
        const float2 a = __half22float2(*(const __half2*)&pk.x);
        const float2 b = __half22float2(*(const __half2*)&pk.y);
        acc.x += v * a.x; acc.y += v * a.y; acc.z += v * b.x; acc.w += v * b.y;
    }
    if (i < e) {
        int2 ed = __ldg(&g_edge[i]);
        uint2 pk = __ldg((const uint2*)(g_FW + (size_t)ed.x * DOUT + dOff) + lane16);
        const float v = sel ? 0.f : __int_as_float(ed.y);
        const float2 a = __half22float2(*(const __half2*)&pk.x);
        const float2 b = __half22float2(*(const __half2*)&pk.y);
        acc.x += v * a.x; acc.y += v * a.y; acc.z += v * b.x; acc.w += v * b.y;
    }

    // combine the two edge-lanes (same d positions)
    acc.x += __shfl_xor_sync(0xffffffffu, acc.x, 16);
    acc.y += __shfl_xor_sync(0xffffffffu, acc.y, 16);
    acc.z += __shfl_xor_sync(0xffffffffu, acc.z, 16);
    acc.w += __shfl_xor_sync(0xffffffffu, acc.w, 16);

    if (sel == 0)
        *(float4*)(out + (size_t)warpId * DOUT + dOff + lane16 * 4) = acc;
}

// ---------------------------------------------------------------------------
// Capture topology (1 extra stream — R13-proven leak-free):
//   s2:   detect -> zero -> hist -> scan1/2/3 -> fill -> wait(evC0)
//         -> scatter_h0 -> evS0
//   main: prep_x -> prep_bt -> gemm -> combine_h0 -> evC0 -> combine_h1
//         -> wait(evS0 ordering not needed; out cols disjoint) -> scatter_h1
//         -> wait(evS0)   (join so the captured graph ends on main)
// ---------------------------------------------------------------------------
extern "C" void kernel_launch(void* const* d_in, const int* in_sizes, int n_in,
                              void* d_out, int out_size) {
    const float* X      = (const float*)d_in[0];
    const void*  A_rows = d_in[1];
    const void*  A_cols = d_in[2];
    const float* A_vals = (const float*)d_in[3];
    const float* basis  = (const float*)d_in[4];
    const float* comp   = (const float*)d_in[5];
    float* out = (float*)d_out;

    cudaFuncSetAttribute(gemm_mma_kernel,
                         cudaFuncAttributeMaxDynamicSharedMemorySize, S_TOTAL);

    cudaStream_t s2;
    cudaStreamCreateWithFlags(&s2, cudaStreamNonBlocking);
    cudaEvent_t evFork, evC0, evS0;
    cudaEventCreateWithFlags(&evFork, cudaEventDisableTiming);
    cudaEventCreateWithFlags(&evC0,   cudaEventDisableTiming);
    cudaEventCreateWithFlags(&evS0,   cudaEventDisableTiming);

    // fork side stream
    cudaEventRecord(evFork, 0);
    cudaStreamWaitEvent(s2, evFork, 0);

    // side stream: dtype detect + CSR sort pipeline
    detect_dtype_kernel<<<1, 1, 0, s2>>>((const unsigned int*)A_rows);
    zero_cnt_kernel<<<(N_NODES + 255) / 256, 256, 0, s2>>>();
    hist_kernel<<<(NNZ + 255) / 256, 256, 0, s2>>>(A_rows);
    scan1_kernel<<<SCAN_BLKS, 1024, 0, s2>>>();
    scan2_kernel<<<1, 64, 0, s2>>>();
    scan3_kernel<<<SCAN_BLKS, 1024, 0, s2>>>();
    fill_kernel<<<(NNZ + 255) / 256, 256, 0, s2>>>(A_rows, A_cols, A_vals);

    // main: preps + gemm + combine half 0
    const int px = (N_PAD * DIN) / 8;
    prep_x_kernel<<<(px + 255) / 256, 256>>>(X);
    const int pb = B_BASES * DOUT * (DIN / 4);
    prep_bt_kernel<<<(pb + 255) / 256, 256>>>(basis);

    dim3 ggrid(M_TILES, B_BASES);
    gemm_mma_kernel<<<ggrid, 256, S_TOTAL>>>(0);

    const int cthreads = N_NODES * 16;
    combine_half_kernel<<<(cthreads + 255) / 256, 256>>>(comp, 0);
    cudaEventRecord(evC0, 0);

    // side stream: scatter half 0 (needs sort done [in-stream] + combine_h0)
    cudaStreamWaitEvent(s2, evC0, 0);
    const long long sthreads = (long long)N_NODES * 32;
    scatter_half_kernel<<<(unsigned)((sthreads + 255) / 256), 256, 0, s2>>>(out, 0);
    cudaEventRecord(evS0, s2);

    // main: combine half 1, scatter half 1 (sort done: scatter_h0 ordering via
    // evC0 is on s2; scatter_h1 needs fill — guaranteed because evS0 is joined
    // below before graph end? No: scatter_h1 needs fill directly.)
    combine_half_kernel<<<(cthreads + 255) / 256, 256>>>(comp, 1);
    // make scatter_h1 depend on the side-stream sort via evS0's predecessor:
    // simplest correct ordering — wait on evS0 is too late (it's after scatter_h0);
    // instead wait on evS0 would serialize. Use a dedicated dependency: scatter_h1
    // only needs g_start/g_edge (fill). evC0->s2 ordering doesn't give main that.
    // So wait on evS0 here WOULD serialize scatter_h1 after scatter_h0 — but both
    // are issue-floor-bound and would share LSU anyway; the overlap win is
    // combine_h1 under scatter_h0. Accept the serialization for correctness.
    cudaStreamWaitEvent(0, evS0, 0);
    scatter_half_kernel<<<(unsigned)((sthreads + 255) / 256), 256>>>(out, 1);
}

// round 17
// speedup vs baseline: 1.1052x; 1.1052x over previous
#include <cuda_runtime.h>
#include <cuda_bf16.h>
#include <cuda_fp16.h>
#include <cstdint>

#define N_NODES 50000
#define N_PAD   50048          // 391 * 128
#define R_REL   16
#define B_BASES 8
#define DIN     128
#define DOUT    128
#define NNZ     1600000
#define M_TILES 391
#define SCAN_BLKS 49           // ceil(50000/1024)

typedef unsigned int uint;

// Scratch: device globals (no allocation allowed)
__device__ __half g_X16[(size_t)N_PAD * DIN];               // 12.8 MB (fp16 X)
__device__ __half g_BT16[B_BASES * DOUT * DIN];             // 256 KB (BT[b][n][k])
__device__ __half g_XB[(size_t)B_BASES * N_NODES * DOUT];   // 102.4 MB (fp16)
__device__ __half g_FW[(size_t)R_REL * N_NODES * DOUT];     // 204.8 MB (fp16)
__device__ int    g_idx64;
// CSR binning scratch
__device__ int   g_cnt[N_NODES];
__device__ int   g_start[N_NODES + 1];
__device__ int   g_cursor[N_NODES];
__device__ int   g_bsum[SCAN_BLKS];
__device__ int2  g_edge[NNZ];

// ---------------------------------------------------------------------------
__device__ __forceinline__ uint32_t smem_u32(const void* p) {
    uint32_t a;
    asm("{ .reg .u64 t; cvta.to.shared.u64 t, %1; cvt.u32.u64 %0, t; }"
        : "=r"(a) : "l"(p));
    return a;
}
__device__ __forceinline__ void ldsm_x4(uint r[4], uint32_t addr) {
    asm volatile("ldmatrix.sync.aligned.m8n8.x4.shared.b16 {%0,%1,%2,%3}, [%4];"
                 : "=r"(r[0]), "=r"(r[1]), "=r"(r[2]), "=r"(r[3]) : "r"(addr));
}
__device__ __forceinline__ void mma_f16(float c[4], const uint a[4], const uint b0, const uint b1) {
    asm volatile("mma.sync.aligned.m16n8k16.row.col.f32.f16.f16.f32 "
                 "{%0,%1,%2,%3},{%4,%5,%6,%7},{%8,%9},{%0,%1,%2,%3};"
                 : "+f"(c[0]), "+f"(c[1]), "+f"(c[2]), "+f"(c[3])
                 : "r"(a[0]), "r"(a[1]), "r"(a[2]), "r"(a[3]), "r"(b0), "r"(b1));
}
__device__ __forceinline__ void cp_async16(uint32_t dst, const void* src) {
    asm volatile("cp.async.cg.shared.global [%0], [%1], 16;" :: "r"(dst), "l"(src));
}
#define CP_COMMIT() asm volatile("cp.async.commit_group;" ::: "memory")
#define CP_WAIT(n)  asm volatile("cp.async.wait_group %0;" :: "n"(n) : "memory")

// ---------------------------------------------------------------------------
__global__ void detect_dtype_kernel(const unsigned int* __restrict__ rows_raw) {
    bool all_hi_zero = true;
    for (int i = 0; i < 64; i++)
        if (rows_raw[2 * i + 1] != 0u) { all_hi_zero = false; break; }
    g_idx64 = all_hi_zero ? 1 : 0;
}

__global__ void zero_cnt_kernel() {
    int i = blockIdx.x * blockDim.x + threadIdx.x;
    if (i < N_NODES) g_cnt[i] = 0;
}

__global__ void hist_kernel(const void* __restrict__ rows) {
    const int e = blockIdx.x * blockDim.x + threadIdx.x;
    if (e >= NNZ) return;
    int row = g_idx64 ? (int)((const unsigned int*)rows)[2 * e]
                      : ((const int*)rows)[e];
    atomicAdd(&g_cnt[row], 1);
}

// --- 3-phase multi-block exclusive scan of g_cnt -> g_start / g_cursor ---
__global__ void __launch_bounds__(1024) scan1_kernel() {
    __shared__ int wsum[32];
    const int tid = threadIdx.x, lane = tid & 31, wid = tid >> 5;
    const int i = blockIdx.x * 1024 + tid;
    int v = (i < N_NODES) ? g_cnt[i] : 0;
    int x = v;
#pragma unroll
    for (int off = 1; off < 32; off <<= 1) {
        int y = __shfl_up_sync(0xffffffffu, x, off);
        if (lane >= off) x += y;
    }
    if (lane == 31) wsum[wid] = x;
    __syncthreads();
    if (wid == 0) {
        int s = wsum[lane];
#pragma unroll
        for (int off = 1; off < 32; off <<= 1) {
            int y = __shfl_up_sync(0xffffffffu, s, off);
            if (lane >= off) s += y;
        }
        wsum[lane] = s;
    }
    __syncthreads();
    const int warpOff = (wid == 0) ? 0 : wsum[wid - 1];
    if (i < N_NODES) g_start[i] = warpOff + x - v;   // block-local exclusive
    if (tid == 0) g_bsum[blockIdx.x] = wsum[31];     // block total
}

__global__ void __launch_bounds__(64) scan2_kernel() {
    __shared__ int s[SCAN_BLKS];
    const int tid = threadIdx.x;
    if (tid < SCAN_BLKS) s[tid] = g_bsum[tid];
    __syncthreads();
    if (tid == 0) {
        int run = 0;
        for (int k = 0; k < SCAN_BLKS; k++) { int v = s[k]; s[k] = run; run += v; }
        g_start[N_NODES] = NNZ;
    }
    __syncthreads();
    if (tid < SCAN_BLKS) g_bsum[tid] = s[tid];       // exclusive block offsets
}

__global__ void __launch_bounds__(1024) scan3_kernel() {
    const int i = blockIdx.x * 1024 + threadIdx.x;
    if (i >= N_NODES) return;
    const int v = g_start[i] + g_bsum[blockIdx.x];
    g_start[i]  = v;
    g_cursor[i] = v;
}

__global__ void fill_kernel(const void* __restrict__ rows,
                            const void* __restrict__ cols,
                            const float* __restrict__ vals) {
    const int e = blockIdx.x * blockDim.x + threadIdx.x;
    if (e >= NNZ) return;
    int row, col;
    if (g_idx64) {
        row = (int)((const unsigned int*)rows)[2 * e];
        col = (int)((const unsigned int*)cols)[2 * e];
    } else {
        row = ((const int*)rows)[e];
        col = ((const int*)cols)[e];
    }
    const int pos = atomicAdd(&g_cursor[row], 1);
    g_edge[pos] = make_int2(col, __float_as_int(vals[e]));
}

// ---------------------------------------------------------------------------
__global__ void prep_x_kernel(const float* __restrict__ X) {
    const int id = blockIdx.x * blockDim.x + threadIdx.x;
    if (id >= (N_PAD * DIN) / 8) return;
    const size_t base = (size_t)id * 8;
    const int row = (int)(base >> 7);
    __half h[8];
    if (row < N_NODES) {
        float v[8];
        *(float4*)&v[0] = *(const float4*)(X + base);
        *(float4*)&v[4] = *(const float4*)(X + base + 4);
#pragma unroll
        for (int i = 0; i < 8; i++) h[i] = __float2half_rn(v[i]);
    } else {
#pragma unroll
        for (int i = 0; i < 8; i++) h[i] = __float2half_rn(0.f);
    }
    *(uint4*)(g_X16 + base) = *(uint4*)h;
}

__global__ void prep_bt_kernel(const float* __restrict__ basis) {
    const int id = blockIdx.x * blockDim.x + threadIdx.x;
    if (id >= B_BASES * DOUT * (DIN / 4)) return;
    const int k4 = (id & 31) * 4;
    const int n  = (id >> 5) & 127;
    const int b  = id >> 12;
    __half h[4];
#pragma unroll
    for (int i = 0; i < 4; i++)
        h[i] = __float2half_rn(basis[(size_t)b * DIN * DOUT + (size_t)(k4 + i) * DOUT + n]);
    const size_t off = (size_t)b * DOUT * DIN + (size_t)n * DIN + k4;
    *(uint2*)(g_BT16 + off) = *(uint2*)h;
}

// ---------------------------------------------------------------------------
// XB[b] = X @ basis[b] via single-product fp16 mma.sync (fp32 accum).
// grid (391, 8), 256 threads, 2 CTAs/SM (48 KB smem), cp.async double buffer.
// B resident full-K (32 KB, 256B rows, swizzle c^(row&7));
// X in 4 k-chunks of 32 (2 x 8 KB, 64B rows, swizzle c^((row>>1)&3)).
// ---------------------------------------------------------------------------
#define S_B    0
#define S_X    32768
#define XBUF   8192
#define S_TOTAL 49152

__global__ void __launch_bounds__(256, 2)
gemm_mma_kernel(int dummy) {
    extern __shared__ __align__(1024) unsigned char smem[];
    const uint32_t sbase = smem_u32(smem);
    const int tid  = threadIdx.x;
    const int wid  = tid >> 5;
    const int lane = tid & 31;
    const int b    = blockIdx.y;
    const int m0   = blockIdx.x * 128;

    const int wm = wid >> 1;          // 0..3 (32 rows)
    const int wn = wid & 1;           // 0..1 (64 cols)

    // --- prologue: async-load B (full K, 2048 chunks, 8/thread), X chunk 0 ---
    {
        const size_t bBase = (size_t)b * DOUT * DIN;
#pragma unroll
        for (int i = 0; i < 8; i++) {
            const int slot = i * 256 + tid;
            const int row  = slot >> 4;
            const int c    = slot & 15;
            const uint32_t dst = (uint32_t)(row * 256 + ((c ^ (row & 7)) << 4));
            cp_async16(sbase + S_B + dst, g_BT16 + bBase + (size_t)row * DIN + c * 8);
        }
    }
    CP_COMMIT();
#pragma unroll
    for (int i = 0; i < 2; i++) {
        const int s2  = i * 256 + tid;
        const int row = s2 >> 2;
        const int c   = s2 & 3;
        const uint32_t dst = (uint32_t)(row * 64 + ((c ^ ((row >> 1) & 3)) << 4));
        cp_async16(sbase + S_X + dst, g_X16 + (size_t)(m0 + row) * DIN + c * 8);
    }
    CP_COMMIT();

    float acc[2][8][4];
#pragma unroll
    for (int mf = 0; mf < 2; mf++)
#pragma unroll
        for (int nf = 0; nf < 8; nf++)
#pragma unroll
            for (int q = 0; q < 4; q++) acc[mf][nf][q] = 0.f;

    const int a_row0 = wm * 32 + (lane & 15);
    const int a_ch   = lane >> 4;
    const int b_row0 = wn * 64 + (lane & 7) + ((lane >> 4) << 3);
    const int b_ch   = (lane >> 3) & 1;

#pragma unroll
    for (int kc = 0; kc < 4; kc++) {
        if (kc < 3) {
            const uint32_t xb = sbase + S_X + ((kc + 1) & 1) * XBUF;
#pragma unroll
            for (int i = 0; i < 2; i++) {
                const int s2  = i * 256 + tid;
                const int row = s2 >> 2;
                const int c   = s2 & 3;
                const uint32_t dst = (uint32_t)(row * 64 + ((c ^ ((row >> 1) & 3)) << 4));
                cp_async16(xb + dst, g_X16 + (size_t)(m0 + row) * DIN + (kc + 1) * 32 + c * 8);
            }
            CP_COMMIT();
            CP_WAIT(1);
        } else {
            CP_WAIT(0);
        }
        __syncthreads();

        const uint32_t xh = sbase + S_X + (kc & 1) * XBUF;

#pragma unroll
        for (int kfi = 0; kfi < 2; kfi++) {
            const int kf = kc * 2 + kfi;
            uint A[2][4];
#pragma unroll
            for (int mf = 0; mf < 2; mf++) {
                const int row = a_row0 + mf * 16;
                const uint32_t addr = (uint32_t)(row * 64 +
                    (((kfi * 2 + a_ch) ^ ((row >> 1) & 3)) << 4));
                ldsm_x4(A[mf], xh + addr);
            }
#pragma unroll
            for (int p = 0; p < 4; p++) {
                const int row = b_row0 + p * 16;
                const uint32_t addr = (uint32_t)(row * 256 +
                    (((kf * 2 + b_ch) ^ (row & 7)) << 4));
                uint B[4];
                ldsm_x4(B, sbase + S_B + addr);
#pragma unroll
                for (int mf = 0; mf < 2; mf++) {
                    mma_f16(acc[mf][2 * p],     A[mf], B[0], B[1]);
                    mma_f16(acc[mf][2 * p + 1], A[mf], B[2], B[3]);
                }
            }
        }
        __syncthreads();
    }

    // --- epilogue: write XB[b] fp16 ---
    __half* outBase = g_XB + (size_t)b * N_NODES * DOUT;
    const int g = lane >> 2;
    const int t2 = (lane & 3) * 2;
#pragma unroll
    for (int mf = 0; mf < 2; mf++) {
        const int r0 = m0 + wm * 32 + mf * 16 + g;
#pragma unroll
        for (int nf = 0; nf < 8; nf++) {
            const int col = wn * 64 + nf * 8 + t2;
            if (r0 < N_NODES) {
                __half2 h = __floats2half2_rn(acc[mf][nf][0], acc[mf][nf][1]);
                *(uint32_t*)(outBase + (size_t)r0 * DOUT + col) = *(uint32_t*)&h;
            }
            if (r0 + 8 < N_NODES) {
                __half2 h = __floats2half2_rn(acc[mf][nf][2], acc[mf][nf][3]);
                *(uint32_t*)(outBase + (size_t)(r0 + 8) * DOUT + col) = *(uint32_t*)&h;
            }
        }
    }
}

// ---------------------------------------------------------------------------
// FW[r][n][d] = sum_b comp[r][b] * XB[b][n][d]   (fp16 in, fp32 math, fp16 out)
// ---------------------------------------------------------------------------
__global__ __launch_bounds__(256)
void combine_kernel(const float* __restrict__ comp) {
    __shared__ float cs[R_REL * B_BASES];
    if (threadIdx.x < R_REL * B_BASES) cs[threadIdx.x] = comp[threadIdx.x];
    __syncthreads();

    const int id = blockIdx.x * blockDim.x + threadIdx.x;
    if (id >= N_NODES * 32) return;
    const int n  = id >> 5;
    const int d4 = (id & 31) * 4;

    float4 xb[8];
#pragma unroll
    for (int b = 0; b < B_BASES; b++) {
        const uint2 pk = __ldg((const uint2*)(g_XB + ((size_t)b * N_NODES + n) * DOUT + d4));
        const float2 a = __half22float2(*(const __half2*)&pk.x);
        const float2 c = __half22float2(*(const __half2*)&pk.y);
        xb[b] = make_float4(a.x, a.y, c.x, c.y);
    }

#pragma unroll
    for (int r = 0; r < R_REL; r++) {
        float4 o = make_float4(0.f, 0.f, 0.f, 0.f);
#pragma unroll
        for (int b = 0; b < B_BASES; b++) {
            const float c = cs[r * B_BASES + b];
            o.x += c * xb[b].x;
            o.y += c * xb[b].y;
            o.z += c * xb[b].z;
            o.w += c * xb[b].w;
        }
        __half2 h0 = __floats2half2_rn(o.x, o.y);
        __half2 h1 = __floats2half2_rn(o.z, o.w);
        uint2 pk;
        pk.x = *(uint32_t*)&h0;
        pk.y = *(uint32_t*)&h1;
        *(uint2*)(g_FW + ((size_t)r * N_NODES + n) * DOUT + d4) = pk;
    }
}

// ---------------------------------------------------------------------------
// Sorted scatter: one warp per output row; fp16 FW gather (8 B/lane/edge),
// unroll-4, fp32 accumulation, single non-atomic row write.
// ---------------------------------------------------------------------------
__device__ __forceinline__ float4 fw_row_f4(int col, int lane) {
    const uint2 pk = __ldg((const uint2*)(g_FW + (size_t)col * DOUT) + lane);
    const float2 a = __half22float2(*(const __half2*)&pk.x);
    const float2 b = __half22float2(*(const __half2*)&pk.y);
    return make_float4(a.x, a.y, b.x, b.y);
}

__global__ void __launch_bounds__(256)
scatter2_kernel(float* __restrict__ out) {
    const int warpId = (blockIdx.x * blockDim.x + threadIdx.x) >> 5;
    if (warpId >= N_NODES) return;
    const int lane = threadIdx.x & 31;

    const int s = g_start[warpId];
    const int e = g_start[warpId + 1];

    float4 acc = make_float4(0.f, 0.f, 0.f, 0.f);
    int i = s;
    for (; i + 4 <= e; i += 4) {
        int2 e0 = g_edge[i], e1 = g_edge[i + 1], e2 = g_edge[i + 2], e3 = g_edge[i + 3];
        float4 f0 = fw_row_f4(e0.x, lane);
        float4 f1 = fw_row_f4(e1.x, lane);
        float4 f2 = fw_row_f4(e2.x, lane);
        float4 f3 = fw_row_f4(e3.x, lane);
        const float v0 = __int_as_float(e0.y), v1 = __int_as_float(e1.y);
        const float v2 = __int_as_float(e2.y), v3 = __int_as_float(e3.y);
        acc.x += v0 * f0.x + v1 * f1.x + v2 * f2.x + v3 * f3.x;
        acc.y += v0 * f0.y + v1 * f1.y + v2 * f2.y + v3 * f3.y;
        acc.z += v0 * f0.z + v1 * f1.z + v2 * f2.z + v3 * f3.z;
        acc.w += v0 * f0.w + v1 * f1.w + v2 * f2.w + v3 * f3.w;
    }
    for (; i < e; i++) {
        int2 ed = g_edge[i];
        float4 f = fw_row_f4(ed.x, lane);
        const float v = __int_as_float(ed.y);
        acc.x += v * f.x; acc.y += v * f.y; acc.z += v * f.z; acc.w += v * f.w;
    }
    *(float4*)(out + (size_t)warpId * DOUT + lane * 4) = acc;
}

// ---------------------------------------------------------------------------
// Fork/join capture (R13 topology — single side stream, known leak-free):
//   s2 (side):  detect -> zero -> hist -> scan1/2/3 -> fill   (evJoin)
//   main:       prep_x -> prep_bt -> gemm -> combine -> wait(evJoin) -> scatter2
// Stream/events created per call (not captured ops, not device allocs;
// intentionally not destroyed — kernel_launch runs only for correctness +
// capture, not per replay).
// ---------------------------------------------------------------------------
extern "C" void kernel_launch(void* const* d_in, const int* in_sizes, int n_in,
                              void* d_out, int out_size) {
    const float* X      = (const float*)d_in[0];
    const void*  A_rows = d_in[1];
    const void*  A_cols = d_in[2];
    const float* A_vals = (const float*)d_in[3];
    const float* basis  = (const float*)d_in[4];
    const float* comp   = (const float*)d_in[5];
    float* out = (float*)d_out;

    cudaFuncSetAttribute(gemm_mma_kernel,
                         cudaFuncAttributeMaxDynamicSharedMemorySize, S_TOTAL);

    cudaStream_t s2;
    cudaStreamCreateWithFlags(&s2, cudaStreamNonBlocking);
    cudaEvent_t evFork, evJoin;
    cudaEventCreateWithFlags(&evFork, cudaEventDisableTiming);
    cudaEventCreateWithFlags(&evJoin, cudaEventDisableTiming);

    // fork side stream immediately
    cudaEventRecord(evFork, 0);
    cudaStreamWaitEvent(s2, evFork, 0);

    // side stream: dtype detect + CSR sort pipeline (multi-block scan)
    detect_dtype_kernel<<<1, 1, 0, s2>>>((const unsigned int*)A_rows);
    zero_cnt_kernel<<<(N_NODES + 255) / 256, 256, 0, s2>>>();
    hist_kernel<<<(NNZ + 255) / 256, 256, 0, s2>>>(A_rows);
    scan1_kernel<<<SCAN_BLKS, 1024, 0, s2>>>();
    scan2_kernel<<<1, 64, 0, s2>>>();
    scan3_kernel<<<SCAN_BLKS, 1024, 0, s2>>>();
    fill_kernel<<<(NNZ + 255) / 256, 256, 0, s2>>>(A_rows, A_cols, A_vals);
    cudaEventRecord(evJoin, s2);

    // main stream: preps + GEMM + combine
    const int px = (N_PAD * DIN) / 8;
    prep_x_kernel<<<(px + 255) / 256, 256>>>(X);
    const int pb = B_BASES * DOUT * (DIN / 4);
    prep_bt_kernel<<<(pb + 255) / 256, 256>>>(basis);

    dim3 ggrid(M_TILES, B_BASES);
    gemm_mma_kernel<<<ggrid, 256, S_TOTAL>>>(0);

    const int cthreads = N_NODES * 32;
    combine_kernel<<<(cthreads + 255) / 256, 256>>>(comp);

    // join, then final scatter
    cudaStreamWaitEvent(0, evJoin, 0);
    const long long sthreads = (long long)N_NODES * 32;
    scatter2_kernel<<<(unsigned)((sthreads + 255) / 256), 256>>>(out);
}